// round 12
// baseline (speedup 1.0000x reference)
#include <cuda_runtime.h>
#include <cuda_fp16.h>
#include <cuda_bf16.h>

// GCN: 3x (h = relu(A_norm @ (h @ W) + b)) -> global mean pool -> MLP.
// SINGLE persistent kernel v2: 888 blocks x 256 thr = 148 SMs x 6 CTAs, ALL
// resident (launch_bounds(256,6) caps regs at 42; smem 16.4KB/CTA). R10's
// mega lost to its own 4-CTA occupancy cap; this one keeps the ~75% occ the
// standalone aggregate achieved while still deleting all launch boundaries.
// Phases (grid barriers between):
//   P0 hist(+rank) + gemm1 | P1 chunk scan | P2 bsum scan | P3 rowptr/dinv
//   P4 scatter | P5 agg1 | P6 gemm2 | P7 agg2 | P8 gemm3 | P9 agg3 | pool+mlp
// Barrier thread does __threadfence() after release (CCTL.IVALL -> drops
// stale L1). Barrier state self-resets so graph replays are identical.
// hW fp16 (128B/row), fp32 accumulate; atomic-free CSR scatter via hist rank.

#define NMAX 50000
#define EMAX 800000

__device__ __half2 g_hW16[NMAX * 32];  // GEMM out / agg in (fp16 pairs)
__device__ float2  g_h2[NMAX * 32];    // agg out / GEMM in (fp32 pairs)
__device__ float   g_dinv[NMAX];
__device__ int     g_deg[NMAX];        // re-zeroed in P3 each run
__device__ int     g_rowptr[NMAX + 1];
__device__ int     g_rank[EMAX];
__device__ int2    g_edges[EMAX];      // {src, f32_bits(norm)}
__device__ int     g_bsum[256];        // chunk sums (196 used)
__device__ int     g_cnt[16];          // barrier arrive counters
__device__ volatile int g_flag[16];    // barrier release flags

// Grid barrier i over nb resident blocks. Self-resetting (resets i-1).
__device__ __forceinline__ void grid_barrier(int i, int nb) {
    __syncthreads();
    if (threadIdx.x == 0) {
        __threadfence();                      // publish phase writes
        int t = atomicAdd(&g_cnt[i], 1);
        if (t == nb - 1) {
            if (i > 0) { g_cnt[i - 1] = 0; *(int*)&g_flag[i - 1] = 0; }
            __threadfence();
            g_flag[i] = 1;
        } else {
            while (g_flag[i] == 0) __nanosleep(32);
        }
        __threadfence();                      // CCTL.IVALL: drop stale L1
    }
    __syncthreads();
}

// Warp-level edge aggregation for one node (4-deep unroll, fp16 gathers).
__device__ __forceinline__ void agg_node(int node, unsigned lane,
                                         float& ax, float& ay) {
    float dn = g_dinv[node];
    float self = dn * dn;
    float2 sv = __half22float2(g_hW16[(unsigned)node * 32u + lane]);
    ax = self * sv.x; ay = self * sv.y;
    int p = g_rowptr[node];
    const int e = g_rowptr[node + 1];
    const int m = p + ((e - p) & ~3);
    for (; p < m; p += 4) {
        int2 r0 = g_edges[p];
        int2 r1 = g_edges[p + 1];
        int2 r2 = g_edges[p + 2];
        int2 r3 = g_edges[p + 3];
        float2 v0 = __half22float2(g_hW16[(unsigned)r0.x * 32u + lane]);
        float2 v1 = __half22float2(g_hW16[(unsigned)r1.x * 32u + lane]);
        float2 v2 = __half22float2(g_hW16[(unsigned)r2.x * 32u + lane]);
        float2 v3 = __half22float2(g_hW16[(unsigned)r3.x * 32u + lane]);
        float w0 = __int_as_float(r0.y), w1 = __int_as_float(r1.y);
        float w2 = __int_as_float(r2.y), w3 = __int_as_float(r3.y);
        ax += w0 * v0.x; ay += w0 * v0.y;
        ax += w1 * v1.x; ay += w1 * v1.y;
        ax += w2 * v2.x; ay += w2 * v2.y;
        ax += w3 * v3.x; ay += w3 * v3.y;
    }
    for (; p < e; p++) {
        int2 r = g_edges[p];
        float w = __int_as_float(r.y);
        float2 v = __half22float2(g_hW16[(unsigned)r.x * 32u + lane]);
        ax += w * v.x; ay += w * v.y;
    }
}

__global__ void __launch_bounds__(256, 6)
gnn_mega_kernel(const float* __restrict__ x, const int* __restrict__ ei,
                const int* __restrict__ batch,
                const float* __restrict__ W1, const float* __restrict__ b1,
                const float* __restrict__ W2, const float* __restrict__ b2,
                const float* __restrict__ W3, const float* __restrict__ b3,
                const float* __restrict__ lw1, const float* __restrict__ lb1,
                const float* __restrict__ lw2, const float* __restrict__ lb2,
                float* __restrict__ out, int N, int E, int G) {
    __shared__ float2 Ws[2048];   // 16KB weight staging (reused per phase)
    __shared__ int sws[32];
    const int tid = threadIdx.x;
    const unsigned lane = tid & 31u;
    const int wid = tid >> 5;
    const int bid = blockIdx.x;
    const int nb = gridDim.x;
    const int gtid = bid * 256 + tid;
    const int nthreads = nb * 256;
    const int gwarp = gtid >> 5;
    const int nwarps = nthreads >> 5;
    const int e4 = (E + 3) / 4;

    // ---- P0: histogram (+rank) and layer-1 GEMM (independent) ----
    for (int u = gtid; u < e4; u += nthreads) {
        int base = u * 4;
        if (base + 3 < E) {
            int4 d = *reinterpret_cast<const int4*>(ei + E + base);
            int4 r;
            r.x = atomicAdd(&g_deg[d.x], 1);
            r.y = atomicAdd(&g_deg[d.y], 1);
            r.z = atomicAdd(&g_deg[d.z], 1);
            r.w = atomicAdd(&g_deg[d.w], 1);
            *reinterpret_cast<int4*>(g_rank + base) = r;
        } else {
            for (int j = 0; j < 4 && base + j < E; j++)
                g_rank[base + j] = atomicAdd(&g_deg[ei[E + base + j]], 1);
        }
    }
    for (int i = tid; i < 32 * 32; i += 256)
        Ws[i] = reinterpret_cast<const float2*>(W1)[i];
    __syncthreads();
    for (int row = gwarp; row < N; row += nwarps) {
        float x0 = x[(unsigned)row * 32u + lane];
        float ax = 0.f, ay = 0.f;
#pragma unroll
        for (int k = 0; k < 32; k++) {
            float xv = __shfl_sync(0xffffffffu, x0, k);
            float2 w = Ws[k * 32 + lane];
            ax += xv * w.x; ay += xv * w.y;
        }
        g_hW16[(unsigned)row * 32u + lane] = __floats2half2_rn(ax, ay);
    }
    grid_barrier(0, nb);

    // ---- P1: per-chunk (256 nodes) reduce + local exclusive scan ----
    const int nchunks = (N + 255) / 256;
    int v = 0, ex_local = 0;
    if (bid < nchunks) {
        int idx = bid * 256 + tid;
        v = (idx < N) ? g_deg[idx] : 0;
        int sc = v;
#pragma unroll
        for (int off = 1; off < 32; off <<= 1) {
            int u = __shfl_up_sync(0xffffffffu, sc, off);
            if (lane >= off) sc += u;
        }
        if (lane == 31) sws[wid] = sc;
        __syncthreads();
        if (wid == 0) {
            int s = (lane < 8) ? sws[lane] : 0;
#pragma unroll
            for (int off = 1; off < 32; off <<= 1) {
                int u = __shfl_up_sync(0xffffffffu, s, off);
                if (lane >= off) s += u;
            }
            sws[lane] = s;
        }
        __syncthreads();
        ex_local = (wid ? sws[wid - 1] : 0) + sc - v;
        if (tid == 0) g_bsum[bid] = sws[7];
        __syncthreads();
    }
    grid_barrier(1, nb);

    // ---- P2: block 0 exclusive-scans the chunk sums ----
    if (bid == 0) {
        int val = (tid < nchunks) ? g_bsum[tid] : 0;
        int sc = val;
#pragma unroll
        for (int off = 1; off < 32; off <<= 1) {
            int u = __shfl_up_sync(0xffffffffu, sc, off);
            if (lane >= off) sc += u;
        }
        if (lane == 31) sws[wid] = sc;
        __syncthreads();
        if (wid == 0) {
            int s = (lane < 8) ? sws[lane] : 0;
#pragma unroll
            for (int off = 1; off < 32; off <<= 1) {
                int u = __shfl_up_sync(0xffffffffu, s, off);
                if (lane >= off) s += u;
            }
            sws[lane] = s;
        }
        __syncthreads();
        int incl = sc + (wid ? sws[wid - 1] : 0);
        if (tid < nchunks) g_bsum[tid] = incl - val;
    }
    grid_barrier(2, nb);

    // ---- P3: rowptr = chunk offset + local; dinv; zero deg ----
    if (bid < nchunks) {
        int idx = bid * 256 + tid;
        if (idx < N) {
            int ex = g_bsum[bid] + ex_local;
            g_rowptr[idx] = ex;
            g_dinv[idx] = rsqrtf((float)(v + 1));   // +1 self loop
            g_deg[idx] = 0;                          // clean for next replay
            if (idx == N - 1) g_rowptr[N] = ex + v;
        }
    }
    grid_barrier(3, nb);

    // ---- P4: scatter (atomic-free): pos = rowptr[dst] + rank ----
    for (int u = gtid; u < e4; u += nthreads) {
        int base = u * 4;
        if (base + 3 < E) {
            int4 s4 = *reinterpret_cast<const int4*>(ei + base);
            int4 d4 = *reinterpret_cast<const int4*>(ei + E + base);
            int4 r4 = *reinterpret_cast<const int4*>(g_rank + base);
            float wx = g_dinv[s4.x] * g_dinv[d4.x];
            float wy = g_dinv[s4.y] * g_dinv[d4.y];
            float wz = g_dinv[s4.z] * g_dinv[d4.z];
            float ww = g_dinv[s4.w] * g_dinv[d4.w];
            g_edges[g_rowptr[d4.x] + r4.x] = make_int2(s4.x, __float_as_int(wx));
            g_edges[g_rowptr[d4.y] + r4.y] = make_int2(s4.y, __float_as_int(wy));
            g_edges[g_rowptr[d4.z] + r4.z] = make_int2(s4.z, __float_as_int(wz));
            g_edges[g_rowptr[d4.w] + r4.w] = make_int2(s4.w, __float_as_int(ww));
        } else {
            for (int j = 0; j < 4 && base + j < E; j++) {
                int s = ei[base + j], d = ei[E + base + j];
                float w = g_dinv[s] * g_dinv[d];
                g_edges[g_rowptr[d] + g_rank[base + j]] =
                    make_int2(s, __float_as_int(w));
            }
        }
    }
    grid_barrier(4, nb);

    // ---- P5/P7/P9: aggregate;  P6/P8: gemm64 ----
    const float* bs[3] = {b1, b2, b3};
    const float* Wn[2] = {W2, W3};
#pragma unroll 1
    for (int layer = 0; layer < 3; layer++) {
        float2 bb = reinterpret_cast<const float2*>(bs[layer])[lane];
        for (int node = gwarp; node < N; node += nwarps) {
            float ax, ay;
            agg_node(node, lane, ax, ay);
            g_h2[(unsigned)node * 32u + lane] =
                make_float2(fmaxf(ax + bb.x, 0.f), fmaxf(ay + bb.y, 0.f));
        }
        grid_barrier(5 + 2 * layer, nb);
        if (layer == 2) break;
        for (int i = tid; i < 2048; i += 256)
            Ws[i] = reinterpret_cast<const float2*>(Wn[layer])[i];
        __syncthreads();
        for (int row = gwarp; row < N; row += nwarps) {
            float2 xr = g_h2[(unsigned)row * 32u + lane];
            float ax = 0.f, ay = 0.f;
#pragma unroll
            for (int k = 0; k < 32; k++) {
                float xk0 = __shfl_sync(0xffffffffu, xr.x, k);
                float xk1 = __shfl_sync(0xffffffffu, xr.y, k);
                float2 w0 = Ws[(2 * k) * 32 + lane];
                float2 w1 = Ws[(2 * k + 1) * 32 + lane];
                ax += xk0 * w0.x + xk1 * w1.x;
                ay += xk0 * w0.y + xk1 * w1.y;
            }
            g_hW16[(unsigned)row * 32u + lane] = __floats2half2_rn(ax, ay);
        }
        grid_barrier(6 + 2 * layer, nb);
    }

    // ---- P10: pool + MLP head (warp per graph; batch sorted) ----
    for (int i = tid; i < 2048; i += 256)
        Ws[i] = reinterpret_cast<const float2*>(lw1)[i];
    __syncthreads();
    for (int g = gwarp; g < G; g += nwarps) {
        int lo = 0, hi = N;
        while (lo < hi) { int m = (lo + hi) >> 1; if (batch[m] < g) lo = m + 1; else hi = m; }
        int start = lo;
        hi = N;
        while (lo < hi) { int m = (lo + hi) >> 1; if (batch[m] < g + 1) lo = m + 1; else hi = m; }
        int end = lo;
        float px = 0.f, py = 0.f;
        for (int i = start; i < end; i++) {
            float2 vv = g_h2[(unsigned)i * 32u + lane];
            px += vv.x; py += vv.y;
        }
        int cnt = end - start;
        float inv = 1.f / (float)(cnt > 0 ? cnt : 1);
        px *= inv; py *= inv;
        float2 lb = reinterpret_cast<const float2*>(lb1)[lane];
        float ax = lb.x, ay = lb.y;
#pragma unroll
        for (int k = 0; k < 32; k++) {
            float pk0 = __shfl_sync(0xffffffffu, px, k);
            float pk1 = __shfl_sync(0xffffffffu, py, k);
            float2 w0 = Ws[(2 * k) * 32 + lane];
            float2 w1 = Ws[(2 * k + 1) * 32 + lane];
            ax += pk0 * w0.x + pk1 * w1.x;
            ay += pk0 * w0.y + pk1 * w1.y;
        }
        ax = fmaxf(ax, 0.f);
        ay = fmaxf(ay, 0.f);
        float4 w2 = reinterpret_cast<const float4*>(lw2)[lane];
        float o0 = ax * w2.x + ay * w2.z;
        float o1 = ax * w2.y + ay * w2.w;
#pragma unroll
        for (int off = 16; off; off >>= 1) {
            o0 += __shfl_down_sync(0xffffffffu, o0, off);
            o1 += __shfl_down_sync(0xffffffffu, o1, off);
        }
        if (lane == 0) {
            out[g * 2 + 0] = o0 + lb2[0];
            out[g * 2 + 1] = o1 + lb2[1];
        }
    }

    // ---- terminal cleanup: reset barrier 9 + self (no one spins on cnt[10])
    __syncthreads();
    if (tid == 0) {
        int t = atomicAdd(&g_cnt[10], 1);
        if (t == nb - 1) {
            g_cnt[9] = 0; *(int*)&g_flag[9] = 0;
            g_cnt[10] = 0;
            __threadfence();
        }
    }
}

// ---------------------------------------------------------------------------
extern "C" void kernel_launch(void* const* d_in, const int* in_sizes, int n_in,
                              void* d_out, int out_size) {
    const float* x     = (const float*)d_in[0];
    const int*   ei    = (const int*)d_in[1];    // int64 ref -> int32 device
    const int*   batch = (const int*)d_in[2];
    const float* W1 = (const float*)d_in[3];
    const float* b1 = (const float*)d_in[4];
    const float* W2 = (const float*)d_in[5];
    const float* b2 = (const float*)d_in[6];
    const float* W3 = (const float*)d_in[7];
    const float* b3 = (const float*)d_in[8];
    const float* lw1 = (const float*)d_in[9];
    const float* lb1 = (const float*)d_in[10];
    const float* lw2 = (const float*)d_in[11];
    const float* lb2 = (const float*)d_in[12];
    float* out = (float*)d_out;

    const int N = in_sizes[0] / 32;
    const int E = in_sizes[1] / 2;
    const int G = out_size / 2;

    // 888 = 148 SMs x 6 CTAs; launch_bounds(256,6) caps regs at 42 so the
    // whole grid is resident in wave 1 -> grid barriers are safe, and the
    // latency-bound gather phases keep ~75% occupancy (R10 had only 47%).
    gnn_mega_kernel<<<888, 256>>>(x, ei, batch, W1, b1, W2, b2, W3, b3,
                                  lw1, lb1, lw2, lb2, out, N, E, G);
}